// round 5
// baseline (speedup 1.0000x reference)
#include <cuda_runtime.h>
#include <math.h>

#define BATCH 4
#define SEQ   512
#define EMB   256
#define NH    8
#define HD    32
#define NC    10
#define NBUCK 32

// ---------------- scratch ----------------
__device__ float g_W1c[NC*NH*HD*HD];
__device__ float g_W2c[NC*NH*HD*HD];
__device__ float g_q [BATCH*NH*SEQ*HD];       // sorted token order
__device__ float g_k [BATCH*NH*SEQ*HD];
__device__ float g_v [BATCH*NH*SEQ*HD];
__device__ float g_qA[BATCH*NH*SEQ*4*HD];     // [bh][pos][tk][n]  sorted
__device__ float g_u [BATCH*NH*SEQ*4*HD];     // [bh][pos][tq][m]  sorted
__device__ float g_ctx[BATCH*SEQ*EMB];        // ORIGINAL order
__device__ unsigned char g_bucket[SEQ*SEQ];
__device__ int g_perm [BATCH*SEQ];
__device__ int g_stype[BATCH*SEQ];
__device__ int g_base [BATCH*4];
__device__ unsigned short g_code [BATCH*SEQ*SEQ];  // cmap*32+bucket, sorted coords
__device__ float          g_masks[BATCH*SEQ*SEQ];  // mask permuted to sorted coords

__device__ __forceinline__ int cmap(int tq, int tk){
    return (tq==0 || tk==0) ? 0 : (tq-1)*3 + tk;
}

// ---------------- K1: softmax(alpha) + combined W ----------------
__global__ void k_prep(const float* __restrict__ W1, const float* __restrict__ a1,
                       const float* __restrict__ W2, const float* __restrict__ a2){
    __shared__ float sa1[NC*3*NH];
    __shared__ float sa2[NC*3*NH];
    int tid = threadIdx.x;
    if (tid < NC*NH){
        int Ci = tid / NH, h = tid % NH;
        {
            float v0=a1[(Ci*3+0)*NH+h], v1=a1[(Ci*3+1)*NH+h], v2=a1[(Ci*3+2)*NH+h];
            float mx=fmaxf(v0,fmaxf(v1,v2));
            float e0=expf(v0-mx), e1=expf(v1-mx), e2=expf(v2-mx);
            float inv=1.0f/(e0+e1+e2);
            sa1[(Ci*3+0)*NH+h]=e0*inv; sa1[(Ci*3+1)*NH+h]=e1*inv; sa1[(Ci*3+2)*NH+h]=e2*inv;
        }
        {
            float v0=a2[(Ci*3+0)*NH+h], v1=a2[(Ci*3+1)*NH+h], v2=a2[(Ci*3+2)*NH+h];
            float mx=fmaxf(v0,fmaxf(v1,v2));
            float e0=expf(v0-mx), e1=expf(v1-mx), e2=expf(v2-mx);
            float inv=1.0f/(e0+e1+e2);
            sa2[(Ci*3+0)*NH+h]=e0*inv; sa2[(Ci*3+1)*NH+h]=e1*inv; sa2[(Ci*3+2)*NH+h]=e2*inv;
        }
    }
    __syncthreads();
    for (int idx=tid; idx<NC*NH*HD*HD; idx+=blockDim.x){
        int n = idx & 31, m = (idx>>5)&31, h=(idx>>10)&7, Ci = idx>>13;
        float acc1=0.f, acc2=0.f;
        #pragma unroll
        for (int b=0;b<3;b++){
            acc1 += W1[((b*NH+h)*HD+m)*HD+n] * sa1[(Ci*3+b)*NH+h];
            acc2 += W2[((b*NH+h)*HD+m)*HD+n] * sa2[(Ci*3+b)*NH+h];
        }
        g_W1c[idx]=acc1; g_W2c[idx]=acc2;
    }
}

// ---------------- K2: T5 buckets ----------------
__global__ void k_bucket(){
    int idx = blockIdx.x*blockDim.x + threadIdx.x;
    if (idx >= SEQ*SEQ) return;
    int q = idx >> 9, k = idx & (SEQ-1);
    int n = q - k;
    int ret = (n < 0) ? 16 : 0;
    int na = n < 0 ? -n : n;
    int bkt;
    if (na < 8) bkt = na;
    else {
        int v = (int)(log((double)na / 8.0) / log(5.0) * 8.0);
        if (v > 7) v = 7;
        bkt = 8 + v;
    }
    g_bucket[idx] = (unsigned char)(ret + bkt);
}

// ---------------- K3: stable counting sort by type ----------------
__global__ void __launch_bounds__(512) k_sort(const int* __restrict__ ts){
    int b = blockIdx.x;
    __shared__ int wcnt[4][16];
    __shared__ int wbase[4][16];
    __shared__ int sbase[4];
    int tid = threadIdx.x, w = tid>>5, lane = tid&31;
    int t = ts[b*SEQ + tid];
    unsigned b0 = __ballot_sync(0xffffffffu, t==0);
    unsigned b1 = __ballot_sync(0xffffffffu, t==1);
    unsigned b2 = __ballot_sync(0xffffffffu, t==2);
    unsigned b3 = __ballot_sync(0xffffffffu, t==3);
    if (lane==0){
        wcnt[0][w]=__popc(b0); wcnt[1][w]=__popc(b1);
        wcnt[2][w]=__popc(b2); wcnt[3][w]=__popc(b3);
    }
    __syncthreads();
    if (tid==0){
        int cum=0;
        for (int tt=0;tt<4;tt++){
            sbase[tt]=cum;
            for (int ww=0;ww<16;ww++){ wbase[tt][ww]=cum; cum+=wcnt[tt][ww]; }
        }
    }
    __syncthreads();
    unsigned mybal = (t==0)?b0:(t==1)?b1:(t==2)?b2:b3;
    int pos = wbase[t][w] + __popc(mybal & ((1u<<lane)-1u));
    g_perm [b*SEQ + pos] = tid;
    g_stype[b*SEQ + pos] = t;
    if (tid<4) g_base[b*4+tid] = sbase[tid];
}

// ---------------- K3b: permute mask + build code table (sorted coords) ----------------
__global__ void __launch_bounds__(256) k_gather(const float* __restrict__ mask){
    int b = blockIdx.y, qs = blockIdx.x;
    int origq = g_perm [b*SEQ+qs];
    int tq    = g_stype[b*SEQ+qs];
    const unsigned char* brow = g_bucket + (size_t)origq*SEQ;
    const float* mrow = mask + ((size_t)(b*SEQ)+origq)*SEQ;
    size_t obase = ((size_t)(b*SEQ)+qs)*SEQ;
    int tid = threadIdx.x;
    #pragma unroll
    for (int j=0;j<2;j++){
        int ks = tid + j*256;
        int origk = g_perm [b*SEQ+ks];
        int tk    = g_stype[b*SEQ+ks];
        int c = cmap(tq, tk);
        g_code [obase+ks] = (unsigned short)(c*NBUCK + brow[origk]);
        g_masks[obase+ks] = mrow[origk];
    }
}

// ---------------- K4: QKV type-pure SGEMM, 64x128 tile, 4x8 micro ----------------
// grid: x=m-chunk(8 of 64 tok), y=b*4+t(16), z=comp*2+ntile(6). block 256.
__global__ void __launch_bounds__(256) k_qkv(const float* __restrict__ x, const float* __restrict__ Wq,
                                             const float* __restrict__ Wk, const float* __restrict__ Wv){
    int b = blockIdx.y >> 2, t = blockIdx.y & 3;
    int base = g_base[b*4+t];
    int end  = (t==3) ? SEQ : g_base[b*4+t+1];
    int m0 = base + blockIdx.x*64;
    if (m0 >= end) return;
    int mtok = end - m0; if (mtok > 64) mtok = 64;

    int comp = blockIdx.z >> 1;
    int n0   = (blockIdx.z & 1) * 128;
    const float* W = ((comp==0)?Wq:(comp==1)?Wk:Wv) + (size_t)t*EMB*EMB + n0;
    float* gout = (comp==0)?g_q:(comp==1)?g_k:g_v;

    __shared__ float sx[16][68];     // [k][m]
    __shared__ float sw[16][128];    // [k][n]
    __shared__ int   sorig[64];

    int tid = threadIdx.x;
    int ty = tid >> 4;   // 0..15 -> 4 token rows
    int tx = tid & 15;   // 0..15 -> 8 cols

    if (tid < 64) sorig[tid] = (tid < mtok) ? g_perm[b*SEQ + m0 + tid] : 0;
    __syncthreads();

    float acc[4][8];
    #pragma unroll
    for (int i=0;i<4;i++)
        #pragma unroll
        for (int j=0;j<8;j++) acc[i][j]=0.f;

    int xm  = tid >> 2;          // 0..63
    int xk4 = (tid & 3) * 4;     // 0,4,8,12
    const float* xrow = x + ((size_t)(b*SEQ) + sorig[xm])*EMB + xk4;
    int wr0 = tid >> 5;          // 0..7
    int wc4 = (tid & 31) * 4;    // 0..124

    for (int kt=0; kt<16; kt++){
        int k0 = kt*16;
        float4 xv = (xm < mtok) ? *(const float4*)(xrow + k0) : make_float4(0,0,0,0);
        float4 wv0 = *(const float4*)(W + (size_t)(k0+wr0  )*EMB + wc4);
        float4 wv1 = *(const float4*)(W + (size_t)(k0+wr0+8)*EMB + wc4);
        __syncthreads();
        sx[xk4+0][xm]=xv.x; sx[xk4+1][xm]=xv.y; sx[xk4+2][xm]=xv.z; sx[xk4+3][xm]=xv.w;
        *(float4*)&sw[wr0  ][wc4] = wv0;
        *(float4*)&sw[wr0+8][wc4] = wv1;
        __syncthreads();
        #pragma unroll
        for (int k=0;k<16;k++){
            float4 a  = *(const float4*)&sx[k][ty*4];
            float4 w0 = *(const float4*)&sw[k][tx*8];
            float4 w1 = *(const float4*)&sw[k][tx*8+4];
            acc[0][0]+=a.x*w0.x; acc[0][1]+=a.x*w0.y; acc[0][2]+=a.x*w0.z; acc[0][3]+=a.x*w0.w;
            acc[0][4]+=a.x*w1.x; acc[0][5]+=a.x*w1.y; acc[0][6]+=a.x*w1.z; acc[0][7]+=a.x*w1.w;
            acc[1][0]+=a.y*w0.x; acc[1][1]+=a.y*w0.y; acc[1][2]+=a.y*w0.z; acc[1][3]+=a.y*w0.w;
            acc[1][4]+=a.y*w1.x; acc[1][5]+=a.y*w1.y; acc[1][6]+=a.y*w1.z; acc[1][7]+=a.y*w1.w;
            acc[2][0]+=a.z*w0.x; acc[2][1]+=a.z*w0.y; acc[2][2]+=a.z*w0.z; acc[2][3]+=a.z*w0.w;
            acc[2][4]+=a.z*w1.x; acc[2][5]+=a.z*w1.y; acc[2][6]+=a.z*w1.z; acc[2][7]+=a.z*w1.w;
            acc[3][0]+=a.w*w0.x; acc[3][1]+=a.w*w0.y; acc[3][2]+=a.w*w0.z; acc[3][3]+=a.w*w0.w;
            acc[3][4]+=a.w*w1.x; acc[3][5]+=a.w*w1.y; acc[3][6]+=a.w*w1.z; acc[3][7]+=a.w*w1.w;
        }
    }
    int ncol = n0 + tx*8;
    int h = ncol >> 5, d = ncol & 31;
    #pragma unroll
    for (int i=0;i<4;i++){
        int row = ty*4 + i;
        if (row < mtok){
            size_t o = ((size_t)((b*NH+h)*SEQ) + m0 + row)*HD + d;
            *(float4*)&gout[o]   = make_float4(acc[i][0],acc[i][1],acc[i][2],acc[i][3]);
            *(float4*)&gout[o+4] = make_float4(acc[i][4],acc[i][5],acc[i][6],acc[i][7]);
        }
    }
}

// ---------------- K5: qA/u with register-resident W ----------------
__global__ void __launch_bounds__(256) k_qau(){
    int bh = blockIdx.y, b = bh>>3, h = bh&7;
    int t  = blockIdx.z;
    int base = g_base[b*4+t];
    int end  = (t==3) ? SEQ : g_base[b*4+t+1];
    int pos0 = base + blockIdx.x*64;
    if (pos0 >= end) return;
    int n = end - pos0; if (n > 64) n = 64;

    __shared__ float sq[64*HD];
    __shared__ float sv[64*HD];
    int tid = threadIdx.x, w = tid>>5, lane = tid&31;

    {
        const float4* qg = (const float4*)(g_q + (size_t)(bh*SEQ+pos0)*HD);
        const float4* vg = (const float4*)(g_v + (size_t)(bh*SEQ+pos0)*HD);
        float4* sq4 = (float4*)sq; float4* sv4 = (float4*)sv;
        int lim = n*HD/4;
        for (int i=tid;i<512;i+=256){
            sq4[i] = (i<lim) ? qg[i] : make_float4(0,0,0,0);
            sv4[i] = (i<lim) ? vg[i] : make_float4(0,0,0,0);
        }
    }
    float wr[32];
    bool isA = (w < 4);
    int slot = isA ? w : (w-4);
    int cc = isA ? cmap(t, slot) : cmap(slot, t);
    const float* wsrc = (isA ? g_W1c : g_W2c) + ((size_t)(cc*NH+h)*HD)*HD + lane;
    #pragma unroll
    for (int m=0;m<32;m++) wr[m] = wsrc[m*HD];
    __syncthreads();

    const float* tile = isA ? sq : sv;
    float* gdst = isA ? g_qA : g_u;
    for (int p=0;p<n;p++){
        const float* r = tile + p*HD;
        float a0=0,a1=0,a2=0,a3=0;
        #pragma unroll
        for (int m=0;m<32;m+=4){
            a0 += r[m  ]*wr[m  ];
            a1 += r[m+1]*wr[m+1];
            a2 += r[m+2]*wr[m+2];
            a3 += r[m+3]*wr[m+3];
        }
        gdst[((size_t)(bh*SEQ + pos0 + p)*4 + slot)*HD + lane] = (a0+a1)+(a2+a3);
    }
}

// ---------------- K6: fused scores + softmax + ctx (flash-style) ----------------
// grid (16, 32), block 256. dynamic smem.
// layout (floats): qA[4096] | s[32*260] | u/ktile[9216] | rp[320]
#define OFF_QA 0
#define OFF_S  4096
#define OFF_U  (4096+32*260)
#define OFF_RP (OFF_U+9216)
#define ATTN_SMEM_FLOATS (OFF_RP+320)

__global__ void __launch_bounds__(256) k_attn(const float* __restrict__ rp){
    extern __shared__ float sm[];
    float* s_qA = sm + OFF_QA;
    float* s_s  = sm + OFF_S;     // [32][260]
    float* s_u  = sm + OFF_U;     // k-tile stage (256x36) OR u tile (64x36 / 64x132)
    float* s_rp = sm + OFF_RP;
    __shared__ float s_M[32], s_Sum[32], s_al[32];
    __shared__ int   s_tq[32], s_oq[32];

    int bh = blockIdx.y, b = bh>>3, h = bh&7;
    int q0 = blockIdx.x*32;
    int tid = threadIdx.x, w = tid>>5, lane = tid&31;

    {   // qA tile: 32 q x 128 floats
        const float4* src = (const float4*)(g_qA + (size_t)(bh*SEQ+q0)*4*HD);
        float4* dst = (float4*)s_qA;
        #pragma unroll
        for (int j=0;j<4;j++) dst[tid + j*256] = src[tid + j*256];
    }
    for (int i=tid;i<NC*NBUCK;i+=256) s_rp[i] = rp[i*NH + h];
    if (tid<32){
        s_tq[tid]=g_stype[b*SEQ+q0+tid];
        s_oq[tid]=g_perm [b*SEQ+q0+tid];
        s_M[tid]=-1e30f; s_Sum[tid]=0.f;
    }
    __syncthreads();

    bool fast = (s_tq[0] == s_tq[31]);
    int t0 = s_tq[0];
    int qc = tid>>3;            // ctx q row 0..31
    int m4 = (tid&7)*4;         // ctx m cols
    int tqc = s_tq[qc];
    float acc0=0,acc1=0,acc2=0,acc3=0;

    const float scale = 0.17677669529663687f;

    for (int tile=0; tile<2; tile++){
        int kbase = tile*256;
        // --- stage k tile (coalesced) into s_u: 256 rows x 32, stride 36 ---
        {
            const float4* src = (const float4*)(g_k + (size_t)(bh*SEQ+kbase)*HD);
            #pragma unroll
            for (int j=0;j<8;j++){
                int i = tid + j*256;          // 0..2047 float4
                int kk = i>>3, c4 = (i&7)*4;
                *(float4*)&s_u[kk*36 + c4] = src[i];
            }
        }
        __syncthreads();
        // --- kv regs for this warp's 32-k chunk ---
        int kloc = w*32 + lane;
        int kp = kbase + kloc;
        float kv[HD];
        {
            const float* kr = s_u + kloc*36;
            #pragma unroll
            for (int j=0;j<8;j++){
                float4 t4 = *(const float4*)(kr + j*4);
                kv[4*j]=t4.x; kv[4*j+1]=t4.y; kv[4*j+2]=t4.z; kv[4*j+3]=t4.w;
            }
        }
        int tkk = g_stype[b*SEQ + kp];
        const unsigned short* crow = g_code  + ((size_t)(b*SEQ+q0))*SEQ + kp;
        const float*          mrow = g_masks + ((size_t)(b*SEQ+q0))*SEQ + kp;
        const float* qab = s_qA + tkk*HD;
        // --- scores into s_s[qi][kloc] ---
        #pragma unroll 2
        for (int qi=0;qi<32;qi++){
            const float* qa = qab + qi*4*HD;
            float a0=0,a1=0,a2=0,a3=0;
            #pragma unroll
            for (int j=0;j<HD;j+=4){
                a0 += qa[j  ]*kv[j  ];
                a1 += qa[j+1]*kv[j+1];
                a2 += qa[j+2]*kv[j+2];
                a3 += qa[j+3]*kv[j+3];
            }
            float bias = s_rp[crow[(size_t)qi*SEQ]];
            float mv   = mrow[(size_t)qi*SEQ];
            s_s[qi*260 + kloc] = ((a0+a1)+(a2+a3))*scale + bias + mv;
        }
        __syncthreads();
        // --- online softmax update: warp w owns rows 4w..4w+3 ---
        #pragma unroll
        for (int rr=0; rr<4; rr++){
            int r = w*4 + rr;
            float* row = s_s + r*260 + lane*8;
            float4 v0 = *(float4*)row;
            float4 v1 = *(float4*)(row+4);
            float m = fmaxf(fmaxf(fmaxf(v0.x,v0.y),fmaxf(v0.z,v0.w)),
                            fmaxf(fmaxf(v1.x,v1.y),fmaxf(v1.z,v1.w)));
            #pragma unroll
            for (int o=16;o;o>>=1) m = fmaxf(m, __shfl_xor_sync(0xffffffffu,m,o));
            float Mold = s_M[r];
            float Mnew = fmaxf(Mold, m);
            v0.x=__expf(v0.x-Mnew); v0.y=__expf(v0.y-Mnew); v0.z=__expf(v0.z-Mnew); v0.w=__expf(v0.w-Mnew);
            v1.x=__expf(v1.x-Mnew); v1.y=__expf(v1.y-Mnew); v1.z=__expf(v1.z-Mnew); v1.w=__expf(v1.w-Mnew);
            float s = (v0.x+v0.y)+(v0.z+v0.w)+(v1.x+v1.y)+(v1.z+v1.w);
            #pragma unroll
            for (int o=16;o;o>>=1) s += __shfl_xor_sync(0xffffffffu,s,o);
            *(float4*)row = v0; *(float4*)(row+4) = v1;
            if (lane==0){
                float al = __expf(Mold - Mnew);
                s_M[r] = Mnew;
                s_Sum[r] = s_Sum[r]*al + s;
                s_al[r] = al;
            }
        }
        __syncthreads();
        // --- ctx accumulate (4 sub-chunks of 64 k) ---
        {
            float al = s_al[qc];
            acc0*=al; acc1*=al; acc2*=al; acc3*=al;
        }
        for (int sub=0; sub<4; sub++){
            __syncthreads();   // previous readers done (also covers s_al read vs nothing)
            if (fast){
                const float4* src = (const float4*)(g_u + ((size_t)(bh*SEQ + kbase + sub*64))*4*HD + t0*HD);
                #pragma unroll
                for (int j=0;j<2;j++){
                    int i = tid + j*256;          // 512 float4
                    int kk = i>>3, c4 = (i&7)*4;
                    *(float4*)&s_u[kk*36 + c4] = src[(size_t)kk*32 + (c4>>2)];
                }
            } else {
                const float4* src = (const float4*)(g_u + ((size_t)(bh*SEQ + kbase + sub*64))*4*HD);
                #pragma unroll
                for (int j=0;j<8;j++){
                    int i = tid + j*256;          // 2048 float4
                    int kk = i>>5, c4 = (i&31)*4;
                    *(float4*)&s_u[kk*132 + c4] = src[(size_t)kk*32 + (c4>>2)];
                }
            }
            __syncthreads();
            const float* prow = s_s + qc*260 + sub*64;
            if (fast){
                #pragma unroll 4
                for (int kk=0;kk<64;kk++){
                    float p = prow[kk];
                    float4 u = *(const float4*)&s_u[kk*36 + m4];
                    acc0 += p*u.x; acc1 += p*u.y; acc2 += p*u.z; acc3 += p*u.w;
                }
            } else {
                int ub = tqc*HD + m4;
                #pragma unroll 4
                for (int kk=0;kk<64;kk++){
                    float p = prow[kk];
                    float4 u = *(const float4*)&s_u[kk*132 + ub];
                    acc0 += p*u.x; acc1 += p*u.y; acc2 += p*u.z; acc3 += p*u.w;
                }
            }
        }
        __syncthreads();   // protect s_s / s_u before next tile
    }
    float inv = 1.0f / s_Sum[qc];
    int oq = s_oq[qc];
    *(float4*)&g_ctx[((size_t)(b*SEQ+oq))*EMB + h*HD + m4] =
        make_float4(acc0*inv, acc1*inv, acc2*inv, acc3*inv);
}

// ---------------- K8: residual + LayerNorm ----------------
__global__ void __launch_bounds__(256) k_ln(const float* __restrict__ x,
                                            const float* __restrict__ gamma,
                                            const float* __restrict__ beta,
                                            float* __restrict__ out){
    int tok = blockIdx.x;
    int tid = threadIdx.x;
    float xv = g_ctx[(size_t)tok*EMB+tid] + x[(size_t)tok*EMB+tid];
    float s = xv;
    #pragma unroll
    for (int o=16;o;o>>=1) s += __shfl_xor_sync(0xffffffffu,s,o);
    __shared__ float r1[8];
    if ((tid&31)==0) r1[tid>>5]=s;
    __syncthreads();
    float tot=0.f;
    #pragma unroll
    for (int i=0;i<8;i++) tot += r1[i];
    float mu = tot*(1.0f/EMB);
    float d = xv - mu;
    float s2 = d*d;
    #pragma unroll
    for (int o=16;o;o>>=1) s2 += __shfl_xor_sync(0xffffffffu,s2,o);
    __shared__ float r2[8];
    if ((tid&31)==0) r2[tid>>5]=s2;
    __syncthreads();
    float tot2=0.f;
    #pragma unroll
    for (int i=0;i<8;i++) tot2 += r2[i];
    float var = tot2*(1.0f/EMB);
    out[(size_t)tok*EMB+tid] = d * rsqrtf(var + 1e-12f) * gamma[tid] + beta[tid];
}

// ---------------- launch ----------------
extern "C" void kernel_launch(void* const* d_in, const int* in_sizes, int n_in,
                              void* d_out, int out_size){
    const float* x    = (const float*)d_in[0];
    const float* mask = (const float*)d_in[1];
    const int*   ts   = (const int*)  d_in[2];
    const float* Wq   = (const float*)d_in[3];
    const float* Wk   = (const float*)d_in[4];
    const float* Wv   = (const float*)d_in[5];
    const float* W1   = (const float*)d_in[6];
    const float* a1   = (const float*)d_in[7];
    const float* W2   = (const float*)d_in[8];
    const float* a2   = (const float*)d_in[9];
    const float* rp   = (const float*)d_in[10];
    const float* gam  = (const float*)d_in[11];
    const float* bet  = (const float*)d_in[12];
    float* out = (float*)d_out;

    int attn_smem = ATTN_SMEM_FLOATS * 4;
    cudaFuncSetAttribute(k_attn, cudaFuncAttributeMaxDynamicSharedMemorySize, attn_smem);

    k_prep  <<<1, 256>>>(W1, a1, W2, a2);
    k_bucket<<<(SEQ*SEQ+255)/256, 256>>>();
    k_sort  <<<BATCH, 512>>>(ts);
    k_gather<<<dim3(SEQ, BATCH), 256>>>(mask);
    k_qkv   <<<dim3(8, 16, 6), 256>>>(x, Wq, Wk, Wv);
    k_qau   <<<dim3(8, BATCH*NH, 4), 256>>>();
    k_attn  <<<dim3(SEQ/32, BATCH*NH), 256, attn_smem>>>(rp);
    k_ln    <<<BATCH*SEQ, 256>>>(x, gam, bet, out);
}